// round 1
// baseline (speedup 1.0000x reference)
#include <cuda_runtime.h>

#define N_NODES 16000
#define DIM 128
#define MAXZ 8192
#define ROWS 32

// -------- device scratch (no allocations allowed) --------
__device__ float g_S[DIM];        // column sums of h
__device__ int   g_zcount;        // number of exact zeros found in g
__device__ int2  g_zlist[MAXZ];   // (i, j) of each zero: g[i*N + j] == 0

// -------- reset scratch (determinism: every call starts clean) --------
__global__ void k_init() {
    int t = threadIdx.x;
    if (t < DIM) g_S[t] = 0.f;
    if (t == 0) g_zcount = 0;
}

// -------- S[d] = sum_i h[i,d] --------
__global__ void __launch_bounds__(256) k_colsum(const float* __restrict__ h) {
    int t = threadIdx.x;
    int col = t & (DIM - 1);
    int r = blockIdx.x * 2 + (t >> 7);
    float s = 0.f;
    for (; r < N_NODES; r += 256)
        s += h[(long)r * DIM + col];
    atomicAdd(&g_S[col], s);
}

// -------- stream 1 GB of g, record the rare exact zeros --------
__global__ void __launch_bounds__(256) k_scan(const float4* __restrict__ g4) {
    const long n4 = (long)N_NODES * N_NODES / 4;   // 64,000,000
    const long stride = (long)gridDim.x * blockDim.x;
    long base = (long)blockIdx.x * blockDim.x + threadIdx.x;
    for (long v0 = base; v0 < n4; v0 += 4 * stride) {
        #pragma unroll
        for (int u = 0; u < 4; u++) {
            long v = v0 + (long)u * stride;
            if (v < n4) {
                float4 x = __ldcs(&g4[v]);
                // bitwise-| to keep the fast path branch-free
                if ((x.x == 0.f) | (x.y == 0.f) | (x.z == 0.f) | (x.w == 0.f)) {
                    float vals[4] = {x.x, x.y, x.z, x.w};
                    #pragma unroll
                    for (int k = 0; k < 4; k++) {
                        if (vals[k] == 0.f) {
                            long idx = v * 4 + k;
                            int i = (int)(idx / N_NODES);
                            int j = (int)(idx - (long)i * N_NODES);
                            int s = atomicAdd(&g_zcount, 1);
                            if (s < MAXZ) g_zlist[s] = make_int2(i, j);
                        }
                    }
                }
            }
        }
    }
}

// -------- fused: y = h + S - corrections; out = relu(relu(y@W1+b1)@W2+b2) --------
__global__ void __launch_bounds__(256) k_mlp(
    const float* __restrict__ h,
    const float* __restrict__ W1, const float* __restrict__ b1,
    const float* __restrict__ W2, const float* __restrict__ b2,
    float* __restrict__ out)
{
    extern __shared__ float sm[];
    float* W1s = sm;                    // 128*128
    float* W2s = W1s + DIM * DIM;       // 128*128
    float* Ys  = W2s + DIM * DIM;       // ROWS*128 (aliased as Z1 after layer 1)
    float* b1s = Ys + ROWS * DIM;       // 128
    float* b2s = b1s + DIM;             // 128

    int tid = threadIdx.x;

    // stage weights/biases
    {
        const float4* a1 = (const float4*)W1;
        const float4* a2 = (const float4*)W2;
        float4* d1 = (float4*)W1s;
        float4* d2 = (float4*)W2s;
        for (int k = tid; k < DIM * DIM / 4; k += 256) d1[k] = a1[k];
        for (int k = tid; k < DIM * DIM / 4; k += 256) d2[k] = a2[k];
        if (tid < DIM) { b1s[tid] = b1[tid]; b2s[tid] = b2[tid]; }
    }

    int j0 = blockIdx.x * ROWS;

    // build Y = h(tile) + S
    for (int k = tid; k < ROWS * DIM; k += 256) {
        int r = k >> 7, d = k & 127;
        Ys[k] = h[(long)(j0 + r) * DIM + d] + g_S[d];
    }
    __syncthreads();

    // sparse corrections: rows j with g[i,j]==0 lose h[i]
    int zc = g_zcount; if (zc > MAXZ) zc = MAXZ;
    for (int z = 0; z < zc; z++) {
        int2 e = g_zlist[z];           // e.x = i, e.y = j
        int rr = e.y - j0;
        if (rr >= 0 && rr < ROWS && tid < DIM)
            Ys[rr * DIM + tid] -= h[(long)e.x * DIM + tid];
    }
    __syncthreads();

    // 4x4 micro-tile per thread: rg = row group (8), cg = col group (32)
    int cg = tid & 31, rg = tid >> 5;
    int c0 = cg * 4, r0 = rg * 4;

    float acc[4][4];

    // ---- layer 1 ----
    {
        float4 bv = *(const float4*)&b1s[c0];
        #pragma unroll
        for (int r = 0; r < 4; r++) {
            acc[r][0] = bv.x; acc[r][1] = bv.y; acc[r][2] = bv.z; acc[r][3] = bv.w;
        }
        #pragma unroll 4
        for (int d = 0; d < DIM; d++) {
            float4 w = *(const float4*)&W1s[d * DIM + c0];
            #pragma unroll
            for (int r = 0; r < 4; r++) {
                float yv = Ys[(r0 + r) * DIM + d];   // warp-broadcast
                acc[r][0] += yv * w.x;
                acc[r][1] += yv * w.y;
                acc[r][2] += yv * w.z;
                acc[r][3] += yv * w.w;
            }
        }
    }
    __syncthreads();
    // write Z1 = relu(layer1) into Ys (alias)
    #pragma unroll
    for (int r = 0; r < 4; r++) {
        float4 zv;
        zv.x = fmaxf(acc[r][0], 0.f);
        zv.y = fmaxf(acc[r][1], 0.f);
        zv.z = fmaxf(acc[r][2], 0.f);
        zv.w = fmaxf(acc[r][3], 0.f);
        *(float4*)&Ys[(r0 + r) * DIM + c0] = zv;
    }
    __syncthreads();

    // ---- layer 2 ----
    {
        float4 bv = *(const float4*)&b2s[c0];
        #pragma unroll
        for (int r = 0; r < 4; r++) {
            acc[r][0] = bv.x; acc[r][1] = bv.y; acc[r][2] = bv.z; acc[r][3] = bv.w;
        }
        #pragma unroll 4
        for (int d = 0; d < DIM; d++) {
            float4 w = *(const float4*)&W2s[d * DIM + c0];
            #pragma unroll
            for (int r = 0; r < 4; r++) {
                float zv = Ys[(r0 + r) * DIM + d];
                acc[r][0] += zv * w.x;
                acc[r][1] += zv * w.y;
                acc[r][2] += zv * w.z;
                acc[r][3] += zv * w.w;
            }
        }
    }
    // outer relu + store
    #pragma unroll
    for (int r = 0; r < 4; r++) {
        float4 o;
        o.x = fmaxf(acc[r][0], 0.f);
        o.y = fmaxf(acc[r][1], 0.f);
        o.z = fmaxf(acc[r][2], 0.f);
        o.w = fmaxf(acc[r][3], 0.f);
        *(float4*)&out[(long)(j0 + r0 + r) * DIM + c0] = o;
    }
}

extern "C" void kernel_launch(void* const* d_in, const int* in_sizes, int n_in,
                              void* d_out, int out_size) {
    const float* g  = (const float*)d_in[0];
    const float* h  = (const float*)d_in[1];
    const float* W1 = (const float*)d_in[2];
    const float* b1 = (const float*)d_in[3];
    const float* W2 = (const float*)d_in[4];
    const float* b2 = (const float*)d_in[5];
    float* out = (float*)d_out;

    const int smem_mlp = (2 * DIM * DIM + ROWS * DIM + 2 * DIM) * (int)sizeof(float); // 148480
    // idempotent, host-side config (not a stream op; capture-safe)
    cudaFuncSetAttribute(k_mlp, cudaFuncAttributeMaxDynamicSharedMemorySize, smem_mlp);

    k_init<<<1, 256>>>();
    k_colsum<<<128, 256>>>(h);
    k_scan<<<1184, 256>>>((const float4*)g);
    k_mlp<<<N_NODES / ROWS, 256, smem_mlp>>>(h, W1, b1, W2, b2, out);
}